// round 3
// baseline (speedup 1.0000x reference)
#include <cuda_runtime.h>

// Correlation layer: out[b, i*41+j, y, x] =
//   (1/576) * sum_c in1[b,c,y,x] * in2[b,c, y-2*(j-10), x-2*(i-10)]
// in1,in2: [4,64,96,160] f32 ; out: [4,1681,96,160] f32
//
// dx always even -> work on float2 (even,odd) pairs with packed fma.rn.f32x2.
// One block per (b, y, j). cp.async double-buffered 8-channel chunks so
// global->smem staging overlaps compute. Register-tiled stencil:
// 10 float2 x 6 displacements per thread, 15-f2 k-window in registers.

#define THREADS 64
#define CK      8           // channels per smem chunk (double buffered)
#define W       160
#define H       96
#define C       64
#define BATCH   4
#define D       41
#define UW      80          // float2 per image row
#define S2W     128         // s2 row width in float2 (su = u2 + 38)
#define TU      10          // float2 per thread along x
#define TI      6           // displacements per thread
#define NTI     7           // 7 * 6 = 42 >= 41

typedef unsigned long long u64;

__device__ __forceinline__ u64 ffma2(u64 a, u64 b, u64 c) {
    u64 d;
    asm("fma.rn.f32x2 %0, %1, %2, %3;" : "=l"(d) : "l"(a), "l"(b), "l"(c));
    return d;
}

__device__ __forceinline__ void cp16(u64* dst, const float* src) {
    unsigned sa = (unsigned)__cvta_generic_to_shared(dst);
    asm volatile("cp.async.cg.shared.global [%0], [%1], 16;\n"
                 :: "r"(sa), "l"(src));
}
__device__ __forceinline__ void cp_commit() {
    asm volatile("cp.async.commit_group;\n" ::);
}
template <int N>
__device__ __forceinline__ void cp_wait() {
    asm volatile("cp.async.wait_group %0;\n" :: "n"(N));
}

__global__ __launch_bounds__(THREADS, 4)
void corr_kernel(const float* __restrict__ in1,
                 const float* __restrict__ in2,
                 float* __restrict__ out) {
    const int j = blockIdx.x;   // dy index, 0..40
    const int y = blockIdx.y;   // 0..95
    const int b = blockIdx.z;   // 0..3
    const int dy = (j - 10) * 2;
    const int y2 = y - dy;
    const int t  = threadIdx.x;

    float* outbase = out + ((size_t)(b * (D * D) + j) * H + y) * W;
    const size_t ostride_i = (size_t)D * H * W;

    if (y2 < 0 || y2 >= H) {
        for (int i = 0; i < D; i++) {
            float4* row = (float4*)(outbase + (size_t)i * ostride_i);
            for (int idx = t; idx < W / 4; idx += THREADS)
                row[idx] = make_float4(0.f, 0.f, 0.f, 0.f);
        }
        return;
    }

    __shared__ u64 s1[2][CK][UW];    // in1 row chunks (float2 pairs)
    __shared__ u64 s2[2][CK][S2W];   // in2 row chunks, zero padded

    const int tu = t & 7;            // 8 u-tiles of 10 float2 -> 80
    const int ti = t >> 3;           // 0..7 ; ti == 7 inactive in compute
    const bool active = (ti < NTI);

    const float* in1base = in1 + ((size_t)(b * C) * H + y)  * W;
    const float* in2base = in2 + ((size_t)(b * C) * H + y2) * W;
    const int crow = H * W;

    // zero the s2 borders once (su < 38 or su >= 118) — never overwritten
    for (int idx = t; idx < 2 * CK * 48; idx += THREADS) {
        int r = idx / 48;
        int z = idx % 48;
        int su = (z < 38) ? z : (118 + z - 38);
        (&s2[0][0][0])[r * S2W + su] = 0ULL;
    }

    u64 acc[TI][TU];
#pragma unroll
    for (int a = 0; a < TI; a++)
#pragma unroll
        for (int q = 0; q < TU; q++) acc[a][q] = 0ULL;

    // k-window base: su_min = 10*tu - 6*ti + 43 (odd) -> abase even, 16B aligned
    const int abase = 10 * tu - 6 * ti + 42;

    // --- cp.async staging: CK rows x 40 x 16B for each of s1, s2 ---
    auto stage = [&](int buf, int c0) {
        const float* p1 = in1base + (size_t)c0 * crow;
        const float* p2 = in2base + (size_t)c0 * crow;
#pragma unroll
        for (int it = 0; it < (CK * 40) / THREADS; it++) {
            int idx = it * THREADS + t;
            int cc = idx / 40;
            int m  = idx % 40;
            cp16(&s1[buf][cc][m * 2],        p1 + (size_t)cc * crow + m * 4);
            cp16(&s2[buf][cc][38 + m * 2],   p2 + (size_t)cc * crow + m * 4);
        }
    };

    const int NCHUNK = C / CK;   // 8
    stage(0, 0);
    cp_commit();

    for (int n = 0; n < NCHUNK; n++) {
        if (n + 1 < NCHUNK) {
            stage((n + 1) & 1, (n + 1) * CK);
            cp_commit();
            cp_wait<1>();
        } else {
            cp_wait<0>();
        }
        __syncthreads();

        const int buf = n & 1;
        if (active) {
#pragma unroll 2
            for (int cc = 0; cc < CK; cc++) {
                u64 q[TU];
                {
                    const ulonglong2* p = (const ulonglong2*)&s1[buf][cc][tu * TU];
#pragma unroll
                    for (int h = 0; h < TU / 2; h++) {
                        ulonglong2 v = p[h];
                        q[2 * h] = v.x; q[2 * h + 1] = v.y;
                    }
                }
                u64 k[16];
                {
                    const ulonglong2* p = (const ulonglong2*)&s2[buf][cc][abase];
#pragma unroll
                    for (int h = 0; h < 8; h++) {
                        ulonglong2 v = p[h];
                        k[2 * h] = v.x; k[2 * h + 1] = v.y;
                    }
                }
#pragma unroll
                for (int ii = 0; ii < TI; ii++)
#pragma unroll
                    for (int uu = 0; uu < TU; uu++)
                        acc[ii][uu] = ffma2(q[uu], k[uu - ii + 6], acc[ii][uu]);
            }
        }
        __syncthreads();
    }

    if (active) {
        const float scale = 1.0f / 576.0f;   // 1 / (64 * 9)
#pragma unroll
        for (int ii = 0; ii < TI; ii++) {
            int i = ti * TI + ii;
            if (i >= D) continue;
            float* row = outbase + (size_t)i * ostride_i + 20 * tu;
#pragma unroll
            for (int uu = 0; uu < TU; uu++) {
                float2 v = *(float2*)&acc[ii][uu];
                v.x *= scale; v.y *= scale;
                *(float2*)(row + 2 * uu) = v;
            }
        }
    }
}

extern "C" void kernel_launch(void* const* d_in, const int* in_sizes, int n_in,
                              void* d_out, int out_size) {
    const float* in1 = (const float*)d_in[0];
    const float* in2 = (const float*)d_in[1];
    dim3 grid(D, H, BATCH);
    corr_kernel<<<grid, THREADS>>>(in1, in2, (float*)d_out);
}

// round 9
// speedup vs baseline: 1.5968x; 1.5968x over previous
#include <cuda_runtime.h>
#include <cstdint>

// Correlation via parity-split banded GEMM on mma.sync (tf32, m16n8k8).
// out[b, i*41+j, y, x] = (1/576) * sum_c in1[b,c,y,x] * in2[b,c,y-2(j-10),x-2(i-10)]
// Parity split: x=2u+p, x2=2v+p, v-u = 10-i in [-30,10].
// Per (b,y,j,p): G_p[u,v] = sum_c A_p[u,c] B_p[v,c];  out[i,2u+p] = G_p[u,u+10-i].

#define W     160
#define H     96
#define CC    64
#define NB    4
#define ND    41
#define CROW  (H*W)
#define ROWSZ 10240          // floats per transposed (b,y) block: 160 rows x 64 c

#define THREADS 320          // 10 warps: (parity, mtile)
#define PAD     68           // smem row pitch (floats) for A/B
#define BROWS   120          // B rows: v in [-30, 90) stored at v+30
#define SPITCH  57           // stripe row pitch

// dynamic smem float offsets
#define FA 0                                     // 2*80*68      = 10880
#define FB 10880                                 // 2*2*120*68   = 32640
#define FS 43520                                 // 2*5*16*57    = 9120
#define SMEM_FLOATS 52640
#define SMEM_BYTES  (SMEM_FLOATS * 4)            // 210560 B

__device__ uint32_t g_in1T[NB * H * ROWSZ];
__device__ uint32_t g_in2T[NB * H * ROWSZ];

__device__ __forceinline__ uint32_t cvt_tf32(float f) {
    uint32_t r;
    asm("cvt.rna.tf32.f32 %0, %1;" : "=r"(r) : "f"(f));
    return r;
}

__device__ __forceinline__ void cp16(uint32_t sdst, const void* src) {
    asm volatile("cp.async.cg.shared.global [%0], [%1], 16;\n" :: "r"(sdst), "l"(src));
}
__device__ __forceinline__ void cp_commit() { asm volatile("cp.async.commit_group;\n" ::); }
template <int N> __device__ __forceinline__ void cp_wait() {
    asm volatile("cp.async.wait_group %0;\n" :: "n"(N));
}

__device__ __forceinline__ void mma_tf32(float* d, const uint32_t* a, const uint32_t* b) {
    asm volatile(
        "mma.sync.aligned.m16n8k8.row.col.f32.tf32.tf32.f32 "
        "{%0,%1,%2,%3}, {%4,%5,%6,%7}, {%8,%9}, {%0,%1,%2,%3};"
        : "+f"(d[0]), "+f"(d[1]), "+f"(d[2]), "+f"(d[3])
        : "r"(a[0]), "r"(a[1]), "r"(a[2]), "r"(a[3]), "r"(b[0]), "r"(b[1]));
}

// ---------- pre-pass: per (b,y), transpose both inputs to [p*80+u][c] tf32 rows ----------
__global__ __launch_bounds__(256)
void prepass(const float* __restrict__ in1, const float* __restrict__ in2) {
    __shared__ uint32_t stag[160 * PAD];
    const int y = blockIdx.x, b = blockIdx.y, t = threadIdx.x;
    for (int s = 0; s < 2; s++) {
        const float* src = (s ? in2 : in1) + ((size_t)(b * CC) * H + y) * W;
        uint32_t* dst = (s ? g_in2T : g_in1T) + (size_t)(b * H + y) * ROWSZ;
        if (s) __syncthreads();
        for (int idx = t; idx < ROWSZ; idx += 256) {
            int c = idx / W;
            int xx = idx - c * W;
            int r = (xx & 1) * 80 + (xx >> 1);
            stag[r * PAD + c] = cvt_tf32(src[(size_t)c * CROW + xx]);
        }
        __syncthreads();
        for (int k = t; k < ROWSZ / 4; k += 256) {
            int row = k >> 4, q = k & 15;
            ((uint4*)dst)[k] = *(const uint4*)&stag[row * PAD + q * 4];
        }
        __syncthreads();
    }
}

// ---------- main kernel: block = (jh, y, b) ----------
__global__ __launch_bounds__(THREADS, 1)
void corr_main(float* __restrict__ out) {
    extern __shared__ float sm[];
    const int jh = blockIdx.x, y = blockIdx.y, b = blockIdx.z;
    const int t = threadIdx.x, wid = t >> 5, lane = t & 31;
    const int g = lane >> 2, tig = lane & 3;

    const int j0 = jh * 21, jcnt = jh ? 20 : 21;
    const size_t ostride_i = (size_t)ND * H * W;
    const float scale = 1.0f / 576.0f;

    uint32_t sb;
    { unsigned long long gg = __cvta_generic_to_shared(sm); sb = (uint32_t)gg; }

    // enumerate valid j; zero-fill invalid j slabs
    int jv[21], y2v[21], nvalid = 0;
    for (int jj = 0; jj < jcnt; jj++) {
        int j = j0 + jj;
        int y2 = y - 2 * (j - 10);
        if (y2 >= 0 && y2 < H) { jv[nvalid] = j; y2v[nvalid] = y2; nvalid++; }
        else {
            float* base = out + (((size_t)(b * ND * ND + j)) * H + y) * W;
            for (int idx = t; idx < ND * (W / 4); idx += THREADS) {
                int i = idx / (W / 4), q = idx - i * (W / 4);
                ((float4*)(base + (size_t)i * ostride_i))[q] = make_float4(0.f, 0.f, 0.f, 0.f);
            }
        }
    }
    if (nvalid == 0) return;

    // stage A (once) + B(0) into buf0
    {
        const uint32_t* A = g_in1T + (size_t)(b * H + y) * ROWSZ;
        const uint32_t* B = g_in2T + (size_t)(b * H + y2v[0]) * ROWSZ;
        for (int k = t; k < 2560; k += THREADS) {          // 160 rows x 16 chunks
            int row = k >> 4, q = k & 15;                  // row = p*80+u
            int p = row >= 80, u = row - p * 80;
            cp16(sb + (FA + row * PAD + q * 4) * 4, A + row * 64 + q * 4);
            int brow = p * BROWS + 30 + u;
            cp16(sb + (FB + brow * PAD + q * 4) * 4, B + row * 64 + q * 4);
        }
        cp_commit();
    }

    const int p  = wid / 5;          // parity
    const int mt = wid - p * 5;      // m-tile
    const int u0 = 16 * mt;

    for (int n = 0; n < nvalid; n++) {
        const int buf = n & 1;
        if (n + 1 < nvalid) {
            const uint32_t* B = g_in2T + (size_t)(b * H + y2v[n + 1]) * ROWSZ;
            const int fb = FB + (buf ^ 1) * 16320;
            for (int k = t; k < 2560; k += THREADS) {
                int row = k >> 4, q = k & 15;
                int pp = row >= 80, u = row - pp * 80;
                int brow = pp * BROWS + 30 + u;
                cp16(sb + (fb + brow * PAD + q * 4) * 4, B + row * 64 + q * 4);
            }
            cp_commit();
            cp_wait<1>();
        } else {
            cp_wait<0>();
        }
        __syncthreads();   // B(n) ready; stripe from j(n-1) fully consumed

        // ---- banded MMA: this warp = (p, mt); 7 n-tiles x 8 k-steps ----
        float acc[7][4];
#pragma unroll
        for (int nt = 0; nt < 7; nt++)
#pragma unroll
            for (int e = 0; e < 4; e++) acc[nt][e] = 0.f;

        const uint32_t* Ab = (const uint32_t*)&sm[FA + (p * 80 + u0 + g) * PAD + tig];
        const uint32_t* Bb = (const uint32_t*)&sm[FB + buf * 16320 + (p * BROWS + u0 + g) * PAD + tig];
#pragma unroll
        for (int kk = 0; kk < 8; kk++) {
            const int c0 = 8 * kk;
            uint32_t a[4];
            a[0] = Ab[c0];
            a[1] = Ab[c0 + 8 * PAD];
            a[2] = Ab[c0 + 4];
            a[3] = Ab[c0 + 8 * PAD + 4];
#pragma unroll
            for (int nt = 0; nt < 7; nt++) {
                // B rows: p*BROWS + u0 + 8*nt + g  (v0 = u0 - 30 + 8*nt, +30 offset)
                uint32_t bfrag[2];
                const uint32_t* bp = Bb + 8 * nt * PAD + c0;
                bfrag[0] = bp[0];
                bfrag[1] = bp[4];
                mma_tf32(acc[nt], a, bfrag);
            }
        }

        // ---- store band to stripe ----
        {
            float* s0 = &sm[FS + ((p * 5 + mt) * 16 + g) * SPITCH + 2 * tig];
            float* s1 = s0 + 8 * SPITCH;
#pragma unroll
            for (int nt = 0; nt < 7; nt++) {
                s0[8 * nt]     = acc[nt][0];
                s0[8 * nt + 1] = acc[nt][1];
                s1[8 * nt]     = acc[nt][2];
                s1[8 * nt + 1] = acc[nt][3];
            }
        }
        __syncthreads();   // stripe complete

        // ---- diagonal gather + coalesced store ----
        {
            const int j = jv[n];
            float* obase = out + (((size_t)(b * ND * ND + j)) * H + y) * W;
            for (int idx = t; idx < ND * 40; idx += THREADS) {
                int i = idx / 40, q = idx - i * 40;
                float4 v4;
                float* vv = (float*)&v4;
#pragma unroll
                for (int e = 0; e < 4; e++) {
                    int x = 4 * q + e;
                    int pp = x & 1, u = x >> 1;
                    int v = u + 10 - i;
                    float val = 0.f;
                    if ((unsigned)v < 80u) {
                        int mtt = u >> 4;
                        val = sm[FS + ((pp * 5 + mtt) * 16 + (u & 15)) * SPITCH
                                 + (v - 16 * mtt + 30)] * scale;
                    }
                    vv[e] = val;
                }
                *(float4*)(obase + (size_t)i * ostride_i + 4 * q) = v4;
            }
        }
        // loop-top __syncthreads protects stripe reuse
    }
}

extern "C" void kernel_launch(void* const* d_in, const int* in_sizes, int n_in,
                              void* d_out, int out_size) {
    const float* in1 = (const float*)d_in[0];
    const float* in2 = (const float*)d_in[1];
    cudaFuncSetAttribute(corr_main, cudaFuncAttributeMaxDynamicSharedMemorySize, SMEM_BYTES);
    prepass<<<dim3(H, NB), 256>>>(in1, in2);
    corr_main<<<dim3(2, H, NB), THREADS, SMEM_BYTES>>>((float*)d_out);
}